// round 1
// baseline (speedup 1.0000x reference)
#include <cuda_runtime.h>
#include <math.h>

#define N 8192
#define D 128
#define TI 128
#define TJ 128
#define NTHREADS 256
#define JSPLIT 2
#define JRANGE (N / JSPLIT)   /* 4096 */
#define NTILES (JRANGE / TJ)  /* 32 */
#define INV_T 14.2857142857142857f
#define THRESH 0.1f

// Scratch (no cudaMalloc allowed): normalized features transposed [D][N] + row accumulators
__device__ float g_fnT[D * N];
__device__ float g_den[N];
__device__ float g_ps[N];
__device__ float g_pc[N];

// ---------------------------------------------------------------------------
// Kernel 1: row-normalize (clamp norm at 1e-8 like torch CosineSimilarity),
// write transposed k-major copy, and zero the per-row accumulators.
// One warp per row, 8 rows per 256-thread block.
// ---------------------------------------------------------------------------
__global__ void prep_kernel(const float* __restrict__ features) {
    int warp = threadIdx.x >> 5;
    int lane = threadIdx.x & 31;
    int row  = blockIdx.x * 8 + warp;

    float4 v = *(const float4*)(features + row * D + lane * 4);
    float ss = v.x * v.x + v.y * v.y + v.z * v.z + v.w * v.w;
    #pragma unroll
    for (int off = 16; off; off >>= 1)
        ss += __shfl_xor_sync(0xffffffffu, ss, off);

    float scale = 1.0f / fmaxf(sqrtf(ss), 1e-8f);
    v.x *= scale; v.y *= scale; v.z *= scale; v.w *= scale;

    int k = lane * 4;
    g_fnT[(k + 0) * N + row] = v.x;
    g_fnT[(k + 1) * N + row] = v.y;
    g_fnT[(k + 2) * N + row] = v.z;
    g_fnT[(k + 3) * N + row] = v.w;

    int gt = blockIdx.x * blockDim.x + threadIdx.x;
    if (gt < N) { g_den[gt] = 0.0f; g_ps[gt] = 0.0f; g_pc[gt] = 0.0f; }
}

// ---------------------------------------------------------------------------
// Kernel 2: fused tiled GEMM (f fn^T) + masked exp-sum / positive-sum epilogue.
// Block = 128 i-rows x 4096 j-range (32 tiles of 128). 256 threads, 8x8
// micro-tile per thread, fma.rn.f32x2 packed accumulation.
// ---------------------------------------------------------------------------
__device__ __forceinline__ unsigned long long pack_dup(float a) {
    unsigned long long r;
    asm("mov.b64 %0, {%1, %1};" : "=l"(r) : "f"(a));
    return r;
}

__global__ void __launch_bounds__(NTHREADS, 1)
main_kernel(const float* __restrict__ labels) {
    extern __shared__ float smem[];
    float* As    = smem;                 // [D][TI]  (k-major, i contiguous)
    float* Bs    = smem + D * TI;        // [D][TJ]  (k-major, j contiguous)
    float* sLabJ = smem + 2 * D * TI;    // [TJ]

    const int tid = threadIdx.x;
    const int tx  = tid & 15;
    const int ty  = tid >> 4;
    const int iBase  = blockIdx.x * TI;
    const int jStart = blockIdx.y * JRANGE;

    // ---- fill A tile once (reused for all 32 j-tiles). Coalesced, conflict-free.
    #pragma unroll
    for (int rep = 0; rep < 16; rep++) {
        int u   = rep * 256 + tid;       // float4 unit
        int k   = u >> 5;                // 32 units per k-row
        int col = (u & 31) << 2;
        *(float4*)(As + k * TI + col) = *(const float4*)(g_fnT + k * N + iBase + col);
    }

    // labels for my 8 i-rows
    float labI[8];
    #pragma unroll
    for (int r = 0; r < 8; r++) labI[r] = labels[iBase + ty * 8 + r];

    float dn[8], ps[8], pc[8];
    #pragma unroll
    for (int r = 0; r < 8; r++) { dn[r] = 0.0f; ps[r] = 0.0f; pc[r] = 0.0f; }

    for (int t = 0; t < NTILES; t++) {
        const int jBase = jStart + t * TJ;

        __syncthreads();   // previous tile's Bs/sLabJ readers done
        #pragma unroll
        for (int rep = 0; rep < 16; rep++) {
            int u   = rep * 256 + tid;
            int k   = u >> 5;
            int col = (u & 31) << 2;
            *(float4*)(Bs + k * TJ + col) = *(const float4*)(g_fnT + k * N + jBase + col);
        }
        if (tid < 32)
            *(float4*)(sLabJ + tid * 4) = *(const float4*)(labels + jBase + tid * 4);
        __syncthreads();

        // ---- mainloop: acc2[r][c2] holds the (c2*2, c2*2+1) pair for row r
        unsigned long long acc2[8][4];
        #pragma unroll
        for (int r = 0; r < 8; r++)
            #pragma unroll
            for (int c = 0; c < 4; c++) acc2[r][c] = 0ull;

        #pragma unroll 8
        for (int k = 0; k < D; k++) {
            const float* ar = As + k * TI + ty * 8;
            float4 a0 = *(const float4*)(ar);
            float4 a1 = *(const float4*)(ar + 4);
            const ulonglong2* br = (const ulonglong2*)(Bs + k * TJ + tx * 8);
            ulonglong2 b01 = br[0];
            ulonglong2 b23 = br[1];
            unsigned long long bb0 = b01.x, bb1 = b01.y, bb2 = b23.x, bb3 = b23.y;
            float a[8] = {a0.x, a0.y, a0.z, a0.w, a1.x, a1.y, a1.z, a1.w};
            #pragma unroll
            for (int r = 0; r < 8; r++) {
                unsigned long long av = pack_dup(a[r]);
                asm("fma.rn.f32x2 %0, %1, %2, %0;" : "+l"(acc2[r][0]) : "l"(av), "l"(bb0));
                asm("fma.rn.f32x2 %0, %1, %2, %0;" : "+l"(acc2[r][1]) : "l"(av), "l"(bb1));
                asm("fma.rn.f32x2 %0, %1, %2, %0;" : "+l"(acc2[r][2]) : "l"(av), "l"(bb2));
                asm("fma.rn.f32x2 %0, %1, %2, %0;" : "+l"(acc2[r][3]) : "l"(av), "l"(bb3));
            }
        }

        // ---- fused epilogue: exp-sum (j != i) and positive-pair stats
        #pragma unroll
        for (int r = 0; r < 8; r++) {
            const int gi = iBase + ty * 8 + r;
            const float li = labI[r];
            float dnl = 0.0f, psl = 0.0f, pcl = 0.0f;
            #pragma unroll
            for (int c2 = 0; c2 < 4; c2++) {
                float s0, s1;
                asm("mov.b64 {%0, %1}, %2;" : "=f"(s0), "=f"(s1) : "l"(acc2[r][c2]));
                int jl = tx * 8 + c2 * 2;
                int gj0 = jBase + jl;
                float lj0 = sLabJ[jl];
                float lj1 = sLabJ[jl + 1];
                float sim0 = s0 * INV_T;
                float sim1 = s1 * INV_T;
                if (gj0 != gi) {
                    dnl += __expf(sim0);
                    if (fabsf(li - lj0) < THRESH) { psl += sim0; pcl += 1.0f; }
                }
                if (gj0 + 1 != gi) {
                    dnl += __expf(sim1);
                    if (fabsf(li - lj1) < THRESH) { psl += sim1; pcl += 1.0f; }
                }
            }
            dn[r] += dnl; ps[r] += psl; pc[r] += pcl;
        }
    }

    // ---- reduce across the 16 tx lanes (xor offsets stay inside each 16-lane half)
    #pragma unroll
    for (int r = 0; r < 8; r++) {
        float a = dn[r], b = ps[r], c = pc[r];
        #pragma unroll
        for (int off = 8; off; off >>= 1) {
            a += __shfl_xor_sync(0xffffffffu, a, off);
            b += __shfl_xor_sync(0xffffffffu, b, off);
            c += __shfl_xor_sync(0xffffffffu, c, off);
        }
        if ((tid & 15) == 0) {
            int gi = iBase + ty * 8 + r;
            atomicAdd(&g_den[gi], a);
            atomicAdd(&g_ps[gi],  b);
            atomicAdd(&g_pc[gi],  c);
        }
    }
}

// ---------------------------------------------------------------------------
// Kernel 3: loss = -mean( ps[i]/pc[i] - log(den[i]) )
// ---------------------------------------------------------------------------
__global__ void finalize_kernel(float* __restrict__ out) {
    __shared__ float red[256];
    float local = 0.0f;
    for (int i = threadIdx.x; i < N; i += 256)
        local += g_ps[i] / g_pc[i] - logf(g_den[i]);
    red[threadIdx.x] = local;
    __syncthreads();
    #pragma unroll
    for (int s = 128; s; s >>= 1) {
        if (threadIdx.x < s) red[threadIdx.x] += red[threadIdx.x + s];
        __syncthreads();
    }
    if (threadIdx.x == 0) out[0] = -red[0] / (float)N;
}

// ---------------------------------------------------------------------------
extern "C" void kernel_launch(void* const* d_in, const int* in_sizes, int n_in,
                              void* d_out, int out_size) {
    const float* features = (const float*)d_in[0];
    const float* labels   = (const float*)d_in[1];
    float* out = (float*)d_out;

    const int smem_bytes = (2 * D * TI + TJ) * (int)sizeof(float);  // 131584
    cudaFuncSetAttribute(main_kernel, cudaFuncAttributeMaxDynamicSharedMemorySize,
                         smem_bytes);

    prep_kernel<<<N / 8, 256>>>(features);
    main_kernel<<<dim3(N / TI, JSPLIT), NTHREADS, smem_bytes>>>(labels);
    finalize_kernel<<<1, 256>>>(out);
}

// round 3
// speedup vs baseline: 4.5687x; 4.5687x over previous
#include <cuda_runtime.h>
#include <cuda_bf16.h>
#include <cstdint>
#include <math.h>

#define N 8192
#define D 128
#define NCTA 148
#define NTOTAL 4096            /* 64 i-tiles x 64 j-tiles */
#define INV_T 14.2857142857142857f
#define THRESH 0.1f

// Scratch (no cudaMalloc allowed)
__device__ __nv_bfloat16 g_fbf[N * D];   // normalized features, bf16, row-major
__device__ float g_den[N];
__device__ float g_ps[N];
__device__ float g_pc[N];

// ---- SMEM layout (bytes) ----
#define SM_A    0           /* 128 x 256B rows, XOR-swizzled (32 KB) */
#define SM_B    32768       /* 2 x 32 KB double-buffered B tiles */
#define SM_LAB  98304       /* 2 x 512B double-buffered label rows */
#define SM_TOTAL 99328

__device__ __forceinline__ uint32_t smem_u32(const void* p) {
    uint32_t a;
    asm("{ .reg .u64 t; cvta.to.shared.u64 t, %1; cvt.u32.u64 %0, t; }" : "=r"(a) : "l"(p));
    return a;
}

#define LDSM_X4(r0, r1, r2, r3, addr) \
    asm volatile("ldmatrix.sync.aligned.m8n8.x4.shared.b16 {%0,%1,%2,%3}, [%4];" \
                 : "=r"(r0), "=r"(r1), "=r"(r2), "=r"(r3) : "r"(addr))

#define MMA16816(d, a, b) \
    asm volatile("mma.sync.aligned.m16n8k16.row.col.f32.bf16.bf16.f32 " \
                 "{%0,%1,%2,%3}, {%4,%5,%6,%7}, {%8,%9}, {%0,%1,%2,%3};" \
                 : "+f"((d)[0]), "+f"((d)[1]), "+f"((d)[2]), "+f"((d)[3]) \
                 : "r"((a)[0]), "r"((a)[1]), "r"((a)[2]), "r"((a)[3]), \
                   "r"((b)[0]), "r"((b)[1]))

#define CP_ASYNC16(dst, src) \
    asm volatile("cp.async.cg.shared.global [%0], [%1], 16;" \
                 :: "r"(dst), "l"(src) : "memory")
#define CP_COMMIT() asm volatile("cp.async.commit_group;" ::: "memory")
#define CP_WAIT0()  asm volatile("cp.async.wait_group 0;" ::: "memory")

// swizzled byte offset of (row, 16B-segment) in a 128x256B tile
__device__ __forceinline__ uint32_t swz(int row, int seg) {
    return (uint32_t)(row * 256 + ((seg ^ (row & 7)) << 4));
}

// cp.async a full 128x256B tile (rows rowBase..+127 of g_fbf) into smem
__device__ __forceinline__ void cp_tile(uint32_t dst_base, int rowBase, int tid) {
    size_t gsrc = __cvta_generic_to_global(g_fbf) + (size_t)rowBase * 256;
    #pragma unroll
    for (int it = 0; it < 8; it++) {
        int u = it * 256 + tid;          // 16B units, 16 per row
        int row = u >> 4, seg = u & 15;
        CP_ASYNC16(dst_base + swz(row, seg), (const void*)(gsrc + (size_t)u * 16));
    }
}

// ---------------------------------------------------------------------------
// Kernel 1: normalize rows (clamp at 1e-8), quantize to bf16, zero accumulators
// ---------------------------------------------------------------------------
__global__ void prep_kernel(const float* __restrict__ features) {
    int warp = threadIdx.x >> 5, lane = threadIdx.x & 31;
    int row = blockIdx.x * 8 + warp;

    float4 v = ((const float4*)(features + row * D))[lane];
    float ss = v.x * v.x + v.y * v.y + v.z * v.z + v.w * v.w;
    #pragma unroll
    for (int off = 16; off; off >>= 1) ss += __shfl_xor_sync(0xffffffffu, ss, off);
    float sc = 1.0f / fmaxf(sqrtf(ss), 1e-8f);

    __nv_bfloat162 p0 = __floats2bfloat162_rn(v.x * sc, v.y * sc);
    __nv_bfloat162 p1 = __floats2bfloat162_rn(v.z * sc, v.w * sc);
    uint2 st;
    st.x = *(const uint32_t*)&p0;
    st.y = *(const uint32_t*)&p1;
    ((uint2*)(g_fbf + (size_t)row * D))[lane] = st;

    int gt = blockIdx.x * blockDim.x + threadIdx.x;
    if (gt < N) { g_den[gt] = 0.0f; g_ps[gt] = 0.0f; g_pc[gt] = 0.0f; }
}

// ---------------------------------------------------------------------------
// Kernel 2: persistent fused HMMA GEMM + masked softmax-denominator /
// positive-pair epilogue. 8 warps in 2x4 grid; warp tile 64x32;
// mma.sync.m16n8k16 bf16 -> f32 register accumulators.
// ---------------------------------------------------------------------------
__global__ void __launch_bounds__(256, 1)
main_kernel(const float* __restrict__ labels) {
    extern __shared__ char smem[];
    const uint32_t sb = smem_u32(smem);
    const int tid  = threadIdx.x;
    const int wid  = tid >> 5;
    const int lane = tid & 31;
    const int wm = wid & 1;          // 0/1 -> m-block of 64
    const int wn = wid >> 1;         // 0..3 -> n-block of 32
    const int quad = lane >> 2;
    const int qt   = lane & 3;

    // --- precomputed ldmatrix per-lane bases ---
    const int rowA = wm * 64 + (lane & 15);
    const int hiA  = lane >> 4;
    const int r7A  = rowA & 7;
    const uint32_t aBase = sb + SM_A + rowA * 256;
    const int g   = lane >> 3;
    const int r8  = lane & 7;
    const int nrowb = wn * 32 + ((g >> 1) << 3) + r8;  // + p*16 later
    const int segbLo = g & 1;
    const uint32_t bRowOff = (uint32_t)(nrowb * 256);

    const int t0 = ((int)blockIdx.x * NTOTAL) / NCTA;
    const int t1 = (((int)blockIdx.x + 1) * NTOTAL) / NCTA;

    int cur_i = t0 >> 6;
    int ibase = cur_i * 128;

    // prologue: A tile + first B tile + first labels
    cp_tile(sb + SM_A, ibase, tid);
    cp_tile(sb + SM_B + (t0 & 1) * 32768, (t0 & 63) * 128, tid);
    if (tid < 32) {
        size_t lsrc = __cvta_generic_to_global(labels) + (size_t)(t0 & 63) * 512;
        CP_ASYNC16(sb + SM_LAB + (t0 & 1) * 512 + tid * 16, (const void*)(lsrc + tid * 16));
    }
    CP_COMMIT();

    // labels for my 8 m-slots (slot = mi*2 + rh; row = wm*64 + mi*16 + quad + rh*8)
    float li[8];
    #pragma unroll
    for (int s2 = 0; s2 < 8; s2++)
        li[s2] = labels[ibase + wm * 64 + (s2 >> 1) * 16 + quad + (s2 & 1) * 8];

    float dn[8], ps[8], pc[8];
    #pragma unroll
    for (int s2 = 0; s2 < 8; s2++) { dn[s2] = 0.0f; ps[s2] = 0.0f; pc[s2] = 0.0f; }

    CP_WAIT0();
    __syncthreads();

    for (int t = t0; t < t1; t++) {
        const int s = t & 1;
        const bool have_next = (t + 1) < t1;

        // prefetch B(t+1) + labels(t+1) (other buffer; its readers finished last iter)
        if (have_next) {
            cp_tile(sb + SM_B + ((t + 1) & 1) * 32768, ((t + 1) & 63) * 128, tid);
            if (tid < 32) {
                size_t lsrc = __cvta_generic_to_global(labels) + (size_t)((t + 1) & 63) * 512;
                CP_ASYNC16(sb + SM_LAB + ((t + 1) & 1) * 512 + tid * 16,
                           (const void*)(lsrc + tid * 16));
            }
            CP_COMMIT();
        }

        // ---- mainloop: 128x128 tile, K=128 ----
        float acc[4][4][4];
        #pragma unroll
        for (int mi = 0; mi < 4; mi++)
            #pragma unroll
            for (int ni = 0; ni < 4; ni++)
                #pragma unroll
                for (int r = 0; r < 4; r++) acc[mi][ni][r] = 0.0f;

        const uint32_t bBase = sb + SM_B + s * 32768 + bRowOff;
        #pragma unroll
        for (int k = 0; k < 8; k++) {
            uint32_t a[4][4];
            #pragma unroll
            for (int mi = 0; mi < 4; mi++) {
                uint32_t addr = aBase + mi * 4096 + ((((k * 2 + hiA) ^ r7A)) << 4);
                LDSM_X4(a[mi][0], a[mi][1], a[mi][2], a[mi][3], addr);
            }
            uint32_t b[4][2];
            #pragma unroll
            for (int p = 0; p < 2; p++) {
                uint32_t addr = bBase + p * 4096 + ((((k * 2 + segbLo) ^ r8)) << 4);
                LDSM_X4(b[2 * p][0], b[2 * p][1], b[2 * p + 1][0], b[2 * p + 1][1], addr);
            }
            #pragma unroll
            for (int mi = 0; mi < 4; mi++)
                #pragma unroll
                for (int ni = 0; ni < 4; ni++)
                    MMA16816(acc[mi][ni], a[mi], b[ni]);
        }

        // ---- fused epilogue from register accumulators ----
        {
            const int jb = (t & 63) * 128;
            const float* slab = (const float*)(smem + SM_LAB + s * 512);
            #pragma unroll
            for (int mi = 0; mi < 4; mi++) {
                #pragma unroll
                for (int rh = 0; rh < 2; rh++) {
                    const int slot = mi * 2 + rh;
                    const int gim = ibase + wm * 64 + mi * 16 + quad + rh * 8;
                    const float lm = li[slot];
                    float dnl = 0.0f, psl = 0.0f, pcl = 0.0f;
                    #pragma unroll
                    for (int ni = 0; ni < 4; ni++) {
                        #pragma unroll
                        for (int c = 0; c < 2; c++) {
                            const int r = rh * 2 + c;
                            float sv = acc[mi][ni][r] * INV_T;
                            const int nl = wn * 32 + ni * 8 + qt * 2 + c;
                            float lj = slab[nl];
                            bool self = (jb + nl) == gim;
                            float e = __expf(sv);
                            dnl += self ? 0.0f : e;
                            bool pos = (fabsf(lm - lj) < THRESH) && !self;
                            psl += pos ? sv : 0.0f;
                            pcl += pos ? 1.0f : 0.0f;
                        }
                    }
                    dn[slot] += dnl; ps[slot] += psl; pc[slot] += pcl;
                }
            }
        }

        const int ni_tile = (t + 1) >> 6;
        const bool ichange = have_next && (ni_tile != cur_i);

        // flush row stats at i-tile boundary / end
        if (ichange || !have_next) {
            #pragma unroll
            for (int s2 = 0; s2 < 8; s2++) {
                float a = dn[s2], b = ps[s2], c = pc[s2];
                a += __shfl_xor_sync(0xffffffffu, a, 1);
                a += __shfl_xor_sync(0xffffffffu, a, 2);
                b += __shfl_xor_sync(0xffffffffu, b, 1);
                b += __shfl_xor_sync(0xffffffffu, b, 2);
                c += __shfl_xor_sync(0xffffffffu, c, 1);
                c += __shfl_xor_sync(0xffffffffu, c, 2);
                if (qt == 0) {
                    int gim = ibase + wm * 64 + (s2 >> 1) * 16 + quad + (s2 & 1) * 8;
                    atomicAdd(&g_den[gim], a);
                    atomicAdd(&g_ps[gim],  b);
                    atomicAdd(&g_pc[gim],  c);
                }
                dn[s2] = 0.0f; ps[s2] = 0.0f; pc[s2] = 0.0f;
            }
        }

        CP_WAIT0();            // B(t+1)/labels(t+1) landed
        __syncthreads();       // and visible to all; epilogue readers of slab done

        if (ichange) {
            cur_i = ni_tile;
            ibase = cur_i * 128;
            cp_tile(sb + SM_A, ibase, tid);
            CP_COMMIT();
            #pragma unroll
            for (int s2 = 0; s2 < 8; s2++)
                li[s2] = labels[ibase + wm * 64 + (s2 >> 1) * 16 + quad + (s2 & 1) * 8];
            CP_WAIT0();
            __syncthreads();
        }
    }
}

// ---------------------------------------------------------------------------
// Kernel 3: loss = -mean( ps[i]/pc[i] - log(den[i]) )
// ---------------------------------------------------------------------------
__global__ void finalize_kernel(float* __restrict__ out) {
    __shared__ float red[256];
    float local = 0.0f;
    for (int i = threadIdx.x; i < N; i += 256)
        local += g_ps[i] / g_pc[i] - logf(g_den[i]);
    red[threadIdx.x] = local;
    __syncthreads();
    #pragma unroll
    for (int sft = 128; sft; sft >>= 1) {
        if (threadIdx.x < sft) red[threadIdx.x] += red[threadIdx.x + sft];
        __syncthreads();
    }
    if (threadIdx.x == 0) out[0] = -red[0] / (float)N;
}

// ---------------------------------------------------------------------------
extern "C" void kernel_launch(void* const* d_in, const int* in_sizes, int n_in,
                              void* d_out, int out_size) {
    const float* features = (const float*)d_in[0];
    const float* labels   = (const float*)d_in[1];
    float* out = (float*)d_out;

    cudaFuncSetAttribute(main_kernel, cudaFuncAttributeMaxDynamicSharedMemorySize, SM_TOTAL);

    prep_kernel<<<N / 8, 256>>>(features);
    main_kernel<<<NCTA, 256, SM_TOTAL>>>(labels);
    finalize_kernel<<<1, 256>>>(out);
}

// round 4
// speedup vs baseline: 5.6616x; 1.2392x over previous
#include <cuda_runtime.h>
#include <cuda_bf16.h>
#include <cstdint>
#include <math.h>

#define N 8192
#define D 128
#define NCTA 148
#define NTT 2080               /* upper-triangle tiles: 64*65/2 */
#define INV_T 14.2857142857142857f
#define THRESH 0.1f

// Scratch (no cudaMalloc allowed)
__device__ __nv_bfloat16 g_fbf[N * D];   // normalized features, bf16, row-major
__device__ float g_den[N];
__device__ float g_ps[N];
__device__ float g_pc[N];
__device__ unsigned int g_done;

// ---- SMEM layout (bytes) ----
#define SM_A    0           /* 128 x 256B rows, XOR-swizzled (32 KB) */
#define SM_B    32768       /* 2 x 32 KB double-buffered B tiles */
#define SM_LAB  98304       /* 2 x 512B double-buffered label rows */
#define SM_TOTAL 99328

__device__ __forceinline__ uint32_t smem_u32(const void* p) {
    uint32_t a;
    asm("{ .reg .u64 t; cvta.to.shared.u64 t, %1; cvt.u32.u64 %0, t; }" : "=r"(a) : "l"(p));
    return a;
}

#define LDSM_X4(r0, r1, r2, r3, addr) \
    asm volatile("ldmatrix.sync.aligned.m8n8.x4.shared.b16 {%0,%1,%2,%3}, [%4];" \
                 : "=r"(r0), "=r"(r1), "=r"(r2), "=r"(r3) : "r"(addr))

#define MMA16816(d, a, b) \
    asm volatile("mma.sync.aligned.m16n8k16.row.col.f32.bf16.bf16.f32 " \
                 "{%0,%1,%2,%3}, {%4,%5,%6,%7}, {%8,%9}, {%0,%1,%2,%3};" \
                 : "+f"((d)[0]), "+f"((d)[1]), "+f"((d)[2]), "+f"((d)[3]) \
                 : "r"((a)[0]), "r"((a)[1]), "r"((a)[2]), "r"((a)[3]), \
                   "r"((b)[0]), "r"((b)[1]))

#define CP_ASYNC16(dst, src) \
    asm volatile("cp.async.cg.shared.global [%0], [%1], 16;" \
                 :: "r"(dst), "l"(src) : "memory")
#define CP_COMMIT() asm volatile("cp.async.commit_group;" ::: "memory")
#define CP_WAIT0()  asm volatile("cp.async.wait_group 0;" ::: "memory")

// swizzled byte offset of (row, 16B-segment) in a 128x256B tile
__device__ __forceinline__ uint32_t swz(int row, int seg) {
    return (uint32_t)(row * 256 + ((seg ^ (row & 7)) << 4));
}

// cp.async a full 128x256B tile (rows rowBase..+127 of g_fbf) into smem
__device__ __forceinline__ void cp_tile(uint32_t dst_base, int rowBase, int tid) {
    size_t gsrc = __cvta_generic_to_global(g_fbf) + (size_t)rowBase * 256;
    #pragma unroll
    for (int it = 0; it < 8; it++) {
        int u = it * 256 + tid;          // 16B units, 16 per row
        int row = u >> 4, seg = u & 15;
        CP_ASYNC16(dst_base + swz(row, seg), (const void*)(gsrc + (size_t)u * 16));
    }
}

// ---------------------------------------------------------------------------
// Kernel 1: normalize rows (clamp at 1e-8), quantize to bf16, zero accumulators
// ---------------------------------------------------------------------------
__global__ void prep_kernel(const float* __restrict__ features) {
    int warp = threadIdx.x >> 5, lane = threadIdx.x & 31;
    int row = blockIdx.x * 8 + warp;

    float4 v = ((const float4*)(features + row * D))[lane];
    float ss = v.x * v.x + v.y * v.y + v.z * v.z + v.w * v.w;
    #pragma unroll
    for (int off = 16; off; off >>= 1) ss += __shfl_xor_sync(0xffffffffu, ss, off);
    float sc = 1.0f / fmaxf(sqrtf(ss), 1e-8f);

    __nv_bfloat162 p0 = __floats2bfloat162_rn(v.x * sc, v.y * sc);
    __nv_bfloat162 p1 = __floats2bfloat162_rn(v.z * sc, v.w * sc);
    uint2 st;
    st.x = *(const uint32_t*)&p0;
    st.y = *(const uint32_t*)&p1;
    ((uint2*)(g_fbf + (size_t)row * D))[lane] = st;

    int gt = blockIdx.x * blockDim.x + threadIdx.x;
    if (gt < N) { g_den[gt] = 0.0f; g_ps[gt] = 0.0f; g_pc[gt] = 0.0f; }
    if (gt == 0) g_done = 0;
}

// ---------------------------------------------------------------------------
// Kernel 2: persistent fused HMMA GEMM over the UPPER-TRIANGLE tile set.
// Off-diagonal tile (ti<tj) feeds both row-i stats (registers) and column-j
// stats (shuffle-reduced, RED to global). Diagonal tiles do row stats with
// self-exclusion. Last CTA performs the final loss reduction.
// ---------------------------------------------------------------------------
__global__ void __launch_bounds__(256, 1)
main_kernel(const float* __restrict__ labels, float* __restrict__ out) {
    extern __shared__ char smem[];
    const uint32_t sb = smem_u32(smem);
    const int tid  = threadIdx.x;
    const int wid  = tid >> 5;
    const int lane = tid & 31;
    const int wm = wid & 1;          // 0/1 -> m-block of 64
    const int wn = wid >> 1;         // 0..3 -> n-block of 32
    const int quad = lane >> 2;
    const int qt   = lane & 3;

    // --- precomputed ldmatrix per-lane bases ---
    const int rowA = wm * 64 + (lane & 15);
    const int hiA  = lane >> 4;
    const int r7A  = rowA & 7;
    const uint32_t aBase = sb + SM_A + rowA * 256;
    const int g   = lane >> 3;
    const int r8  = lane & 7;
    const int nrowb = wn * 32 + ((g >> 1) << 3) + r8;  // + p*16 later
    const int segbLo = g & 1;
    const uint32_t bRowOff = (uint32_t)(nrowb * 256);

    const int t0 = ((int)blockIdx.x * NTT) / NCTA;
    const int t1 = (((int)blockIdx.x + 1) * NTT) / NCTA;

    // map t0 -> (ti, tj) in the upper triangle (row ti has 64-ti tiles)
    int ti = 0, rem = t0;
    while (rem >= 64 - ti) { rem -= 64 - ti; ti++; }
    int tj = ti + rem;
    int ibase = ti * 128;

    // prologue: A tile + first B tile + first labels
    cp_tile(sb + SM_A, ibase, tid);
    cp_tile(sb + SM_B + (t0 & 1) * 32768, tj * 128, tid);
    if (tid < 32) {
        size_t lsrc = __cvta_generic_to_global(labels) + (size_t)tj * 512;
        CP_ASYNC16(sb + SM_LAB + (t0 & 1) * 512 + tid * 16, (const void*)(lsrc + tid * 16));
    }
    CP_COMMIT();

    // labels for my 8 m-slots (slot = mi*2 + rh; row = wm*64 + mi*16 + quad + rh*8)
    float li[8];
    #pragma unroll
    for (int s2 = 0; s2 < 8; s2++)
        li[s2] = labels[ibase + wm * 64 + (s2 >> 1) * 16 + quad + (s2 & 1) * 8];

    float dn[8], ps[8], pc[8];
    #pragma unroll
    for (int s2 = 0; s2 < 8; s2++) { dn[s2] = 0.0f; ps[s2] = 0.0f; pc[s2] = 0.0f; }

    CP_WAIT0();
    __syncthreads();

    for (int t = t0; t < t1; t++) {
        const int s = t & 1;
        const bool have_next = (t + 1) < t1;

        // next tile indices
        int nti = ti, ntj = tj + 1;
        if (ntj == 64) { nti = ti + 1; ntj = nti; }

        // prefetch B(t+1) + labels(t+1)
        if (have_next) {
            cp_tile(sb + SM_B + ((t + 1) & 1) * 32768, ntj * 128, tid);
            if (tid < 32) {
                size_t lsrc = __cvta_generic_to_global(labels) + (size_t)ntj * 512;
                CP_ASYNC16(sb + SM_LAB + ((t + 1) & 1) * 512 + tid * 16,
                           (const void*)(lsrc + tid * 16));
            }
            CP_COMMIT();
        }

        // ---- mainloop: 128x128 tile, K=128 ----
        float acc[4][4][4];
        #pragma unroll
        for (int mi = 0; mi < 4; mi++)
            #pragma unroll
            for (int ni = 0; ni < 4; ni++)
                #pragma unroll
                for (int r = 0; r < 4; r++) acc[mi][ni][r] = 0.0f;

        const uint32_t bBase = sb + SM_B + s * 32768 + bRowOff;
        #pragma unroll
        for (int k = 0; k < 8; k++) {
            uint32_t a[4][4];
            #pragma unroll
            for (int mi = 0; mi < 4; mi++) {
                uint32_t addr = aBase + mi * 4096 + ((((k * 2 + hiA) ^ r7A)) << 4);
                LDSM_X4(a[mi][0], a[mi][1], a[mi][2], a[mi][3], addr);
            }
            uint32_t b[4][2];
            #pragma unroll
            for (int p = 0; p < 2; p++) {
                uint32_t addr = bBase + p * 4096 + ((((k * 2 + segbLo) ^ r8)) << 4);
                LDSM_X4(b[2 * p][0], b[2 * p][1], b[2 * p + 1][0], b[2 * p + 1][1], addr);
            }
            #pragma unroll
            for (int mi = 0; mi < 4; mi++)
                #pragma unroll
                for (int ni = 0; ni < 4; ni++)
                    MMA16816(acc[mi][ni], a[mi], b[ni]);
        }

        // ---- fused epilogue ----
        {
            const int jb = tj * 128;
            const float* slab = (const float*)(smem + SM_LAB + s * 512);

            if (jb == ibase) {
                // diagonal tile: row stats only, with self-exclusion
                #pragma unroll
                for (int mi = 0; mi < 4; mi++) {
                    #pragma unroll
                    for (int rh = 0; rh < 2; rh++) {
                        const int slot = mi * 2 + rh;
                        const int selfnl = wm * 64 + mi * 16 + quad + rh * 8;
                        const float lm = li[slot];
                        float dnl = 0.0f, psl = 0.0f, pcl = 0.0f;
                        #pragma unroll
                        for (int ni = 0; ni < 4; ni++) {
                            #pragma unroll
                            for (int c = 0; c < 2; c++) {
                                float sv = acc[mi][ni][rh * 2 + c] * INV_T;
                                const int nl = wn * 32 + ni * 8 + qt * 2 + c;
                                float lj = slab[nl];
                                bool self = (nl == selfnl);
                                float e = __expf(sv);
                                dnl += self ? 0.0f : e;
                                bool pos = (fabsf(lm - lj) < THRESH) && !self;
                                psl += pos ? sv : 0.0f;
                                pcl += pos ? 1.0f : 0.0f;
                            }
                        }
                        dn[slot] += dnl; ps[slot] += psl; pc[slot] += pcl;
                    }
                }
            } else {
                // off-diagonal tile: row stats + column stats, no self possible
                #pragma unroll
                for (int ni = 0; ni < 4; ni++) {
                    #pragma unroll
                    for (int c = 0; c < 2; c++) {
                        const int nl = wn * 32 + ni * 8 + qt * 2 + c;
                        const float lj = slab[nl];
                        float cdn = 0.0f, cps = 0.0f, cpc = 0.0f;
                        #pragma unroll
                        for (int mi = 0; mi < 4; mi++) {
                            #pragma unroll
                            for (int rh = 0; rh < 2; rh++) {
                                const int slot = mi * 2 + rh;
                                float sv = acc[mi][ni][rh * 2 + c] * INV_T;
                                float e = __expf(sv);
                                dn[slot] += e;
                                cdn += e;
                                bool pos = fabsf(li[slot] - lj) < THRESH;
                                float svp = pos ? sv : 0.0f;
                                float onep = pos ? 1.0f : 0.0f;
                                ps[slot] += svp;  cps += svp;
                                pc[slot] += onep; cpc += onep;
                            }
                        }
                        // reduce column stats across the 8 quad-lanes (stride 4)
                        #pragma unroll
                        for (int off = 4; off <= 16; off <<= 1) {
                            cdn += __shfl_xor_sync(0xffffffffu, cdn, off);
                            cps += __shfl_xor_sync(0xffffffffu, cps, off);
                            cpc += __shfl_xor_sync(0xffffffffu, cpc, off);
                        }
                        if (quad == 0) {
                            atomicAdd(&g_den[jb + nl], cdn);
                            atomicAdd(&g_ps[jb + nl],  cps);
                            atomicAdd(&g_pc[jb + nl],  cpc);
                        }
                    }
                }
            }
        }

        const bool ichange = have_next && (nti != ti);

        // flush row stats at i-row boundary / end
        if (ichange || !have_next) {
            #pragma unroll
            for (int s2 = 0; s2 < 8; s2++) {
                float a = dn[s2], b = ps[s2], c = pc[s2];
                a += __shfl_xor_sync(0xffffffffu, a, 1);
                a += __shfl_xor_sync(0xffffffffu, a, 2);
                b += __shfl_xor_sync(0xffffffffu, b, 1);
                b += __shfl_xor_sync(0xffffffffu, b, 2);
                c += __shfl_xor_sync(0xffffffffu, c, 1);
                c += __shfl_xor_sync(0xffffffffu, c, 2);
                if (qt == 0) {
                    int gim = ibase + wm * 64 + (s2 >> 1) * 16 + quad + (s2 & 1) * 8;
                    atomicAdd(&g_den[gim], a);
                    atomicAdd(&g_ps[gim],  b);
                    atomicAdd(&g_pc[gim],  c);
                }
                dn[s2] = 0.0f; ps[s2] = 0.0f; pc[s2] = 0.0f;
            }
        }

        CP_WAIT0();            // B(t+1)/labels(t+1) landed
        __syncthreads();       // visible to all; slab readers done

        if (ichange) {
            ibase = nti * 128;
            cp_tile(sb + SM_A, ibase, tid);
            CP_COMMIT();
            #pragma unroll
            for (int s2 = 0; s2 < 8; s2++)
                li[s2] = labels[ibase + wm * 64 + (s2 >> 1) * 16 + quad + (s2 & 1) * 8];
            CP_WAIT0();
            __syncthreads();
        }
        ti = nti; tj = ntj;
    }

    // ---- last CTA computes the final loss (threadfence + counter pattern) ----
    __threadfence();
    __syncthreads();
    __shared__ unsigned int s_ticket;
    if (tid == 0) s_ticket = atomicAdd(&g_done, 1u);
    __syncthreads();
    if (s_ticket == NCTA - 1) {
        __threadfence();
        float* red = (float*)smem;
        float local = 0.0f;
        for (int i = tid; i < N; i += 256)
            local += g_ps[i] / g_pc[i] - logf(g_den[i]);
        red[tid] = local;
        __syncthreads();
        #pragma unroll
        for (int sft = 128; sft; sft >>= 1) {
            if (tid < sft) red[tid] += red[tid + sft];
            __syncthreads();
        }
        if (tid == 0) out[0] = -red[0] / (float)N;
    }
}

// ---------------------------------------------------------------------------
extern "C" void kernel_launch(void* const* d_in, const int* in_sizes, int n_in,
                              void* d_out, int out_size) {
    const float* features = (const float*)d_in[0];
    const float* labels   = (const float*)d_in[1];
    float* out = (float*)d_out;

    cudaFuncSetAttribute(main_kernel, cudaFuncAttributeMaxDynamicSharedMemorySize, SM_TOTAL);

    prep_kernel<<<N / 8, 256>>>(features);
    main_kernel<<<NCTA, 256, SM_TOTAL>>>(labels, out);
}

// round 5
// speedup vs baseline: 5.8042x; 1.0252x over previous
#include <cuda_runtime.h>
#include <cuda_bf16.h>
#include <cstdint>
#include <math.h>

#define N 8192
#define D 128
#define NCTA 148
#define NTT 2080               /* upper-triangle tiles: 64*65/2 */
#define NTHR 512
#define INV_T 14.2857142857142857f
#define THRESH 0.1f

// Scratch (no cudaMalloc allowed)
__device__ __nv_bfloat16 g_fbf[N * D];   // normalized features, bf16, row-major
__device__ float g_den[N];
__device__ float g_ps[N];
__device__ float g_pc[N];
__device__ unsigned int g_done;

// ---- SMEM layout (bytes) ----
#define SM_A    0           /* 128 x 256B rows, XOR-swizzled (32 KB) */
#define SM_B    32768       /* 2 x 32 KB double-buffered B tiles */
#define SM_LAB  98304       /* 2 x 512B double-buffered label rows */
#define SM_TOTAL 99328

__device__ __forceinline__ uint32_t smem_u32(const void* p) {
    uint32_t a;
    asm("{ .reg .u64 t; cvta.to.shared.u64 t, %1; cvt.u32.u64 %0, t; }" : "=r"(a) : "l"(p));
    return a;
}

#define LDSM_X4(r0, r1, r2, r3, addr) \
    asm volatile("ldmatrix.sync.aligned.m8n8.x4.shared.b16 {%0,%1,%2,%3}, [%4];" \
                 : "=r"(r0), "=r"(r1), "=r"(r2), "=r"(r3) : "r"(addr))

#define MMA16816(d, a, b) \
    asm volatile("mma.sync.aligned.m16n8k16.row.col.f32.bf16.bf16.f32 " \
                 "{%0,%1,%2,%3}, {%4,%5,%6,%7}, {%8,%9}, {%0,%1,%2,%3};" \
                 : "+f"((d)[0]), "+f"((d)[1]), "+f"((d)[2]), "+f"((d)[3]) \
                 : "r"((a)[0]), "r"((a)[1]), "r"((a)[2]), "r"((a)[3]), \
                   "r"((b)[0]), "r"((b)[1]))

#define CP_ASYNC16(dst, src) \
    asm volatile("cp.async.cg.shared.global [%0], [%1], 16;" \
                 :: "r"(dst), "l"(src) : "memory")
#define CP_COMMIT() asm volatile("cp.async.commit_group;" ::: "memory")
#define CP_WAIT0()  asm volatile("cp.async.wait_group 0;" ::: "memory")

// swizzled byte offset of (row, 16B-segment) in a 128x256B tile
__device__ __forceinline__ uint32_t swz(int row, int seg) {
    return (uint32_t)(row * 256 + ((seg ^ (row & 7)) << 4));
}

// cp.async a full 128x256B tile (rows rowBase..+127 of g_fbf) into smem
__device__ __forceinline__ void cp_tile(uint32_t dst_base, int rowBase, int tid) {
    size_t gsrc = __cvta_generic_to_global(g_fbf) + (size_t)rowBase * 256;
    #pragma unroll
    for (int it = 0; it < 4; it++) {
        int u = it * NTHR + tid;         // 16B units, 16 per row, 2048 total
        int row = u >> 4, seg = u & 15;
        CP_ASYNC16(dst_base + swz(row, seg), (const void*)(gsrc + (size_t)u * 16));
    }
}

// ---------------------------------------------------------------------------
// Kernel 1: normalize rows (clamp at 1e-8), quantize to bf16, zero accumulators
// ---------------------------------------------------------------------------
__global__ void prep_kernel(const float* __restrict__ features) {
    int warp = threadIdx.x >> 5, lane = threadIdx.x & 31;
    int row = blockIdx.x * 8 + warp;

    float4 v = ((const float4*)(features + row * D))[lane];
    float ss = v.x * v.x + v.y * v.y + v.z * v.z + v.w * v.w;
    #pragma unroll
    for (int off = 16; off; off >>= 1) ss += __shfl_xor_sync(0xffffffffu, ss, off);
    float sc = 1.0f / fmaxf(sqrtf(ss), 1e-8f);

    __nv_bfloat162 p0 = __floats2bfloat162_rn(v.x * sc, v.y * sc);
    __nv_bfloat162 p1 = __floats2bfloat162_rn(v.z * sc, v.w * sc);
    uint2 st;
    st.x = *(const uint32_t*)&p0;
    st.y = *(const uint32_t*)&p1;
    ((uint2*)(g_fbf + (size_t)row * D))[lane] = st;

    int gt = blockIdx.x * blockDim.x + threadIdx.x;
    if (gt < N) { g_den[gt] = 0.0f; g_ps[gt] = 0.0f; g_pc[gt] = 0.0f; }
    if (gt == 0) g_done = 0;
}

// ---------------------------------------------------------------------------
// Kernel 2: persistent fused HMMA GEMM over the UPPER-TRIANGLE tile set.
// 512 threads, 16 warps in 4x4 grid, 32x32 warp tiles (4 warps/SMSP for
// latency hiding). Off-diagonal tiles feed row stats (registers) and column
// stats (shuffle + RED). Last CTA does the final loss reduction.
// ---------------------------------------------------------------------------
__global__ void __launch_bounds__(NTHR, 1)
main_kernel(const float* __restrict__ labels, float* __restrict__ out) {
    extern __shared__ char smem[];
    const uint32_t sb = smem_u32(smem);
    const int tid  = threadIdx.x;
    const int wid  = tid >> 5;
    const int lane = tid & 31;
    const int wm = wid & 3;          // 0..3 -> m-block of 32
    const int wn = wid >> 2;         // 0..3 -> n-block of 32
    const int quad = lane >> 2;
    const int qt   = lane & 3;

    // --- precomputed ldmatrix per-lane bases ---
    const int rowA = wm * 32 + (lane & 15);
    const int hiA  = lane >> 4;
    const int r7A  = rowA & 7;
    const uint32_t aBase = sb + SM_A + rowA * 256;
    const int g   = lane >> 3;
    const int r8  = lane & 7;
    const int nrowb = wn * 32 + ((g >> 1) << 3) + r8;  // + p*16 later
    const int segbLo = g & 1;
    const uint32_t bRowOff = (uint32_t)(nrowb * 256);

    const int t0 = ((int)blockIdx.x * NTT) / NCTA;
    const int t1 = (((int)blockIdx.x + 1) * NTT) / NCTA;

    // map t0 -> (ti, tj) in the upper triangle (row ti has 64-ti tiles)
    int ti = 0, rem = t0;
    while (rem >= 64 - ti) { rem -= 64 - ti; ti++; }
    int tj = ti + rem;
    int ibase = ti * 128;

    // prologue: A tile + first B tile + first labels
    cp_tile(sb + SM_A, ibase, tid);
    cp_tile(sb + SM_B + (t0 & 1) * 32768, tj * 128, tid);
    if (tid < 32) {
        size_t lsrc = __cvta_generic_to_global(labels) + (size_t)tj * 512;
        CP_ASYNC16(sb + SM_LAB + (t0 & 1) * 512 + tid * 16, (const void*)(lsrc + tid * 16));
    }
    CP_COMMIT();

    // labels for my 4 m-slots (slot = mi*2 + rh; row = wm*32 + mi*16 + quad + rh*8)
    float li[4];
    #pragma unroll
    for (int s2 = 0; s2 < 4; s2++)
        li[s2] = labels[ibase + wm * 32 + (s2 >> 1) * 16 + quad + (s2 & 1) * 8];

    float dn[4], ps[4], pc[4];
    #pragma unroll
    for (int s2 = 0; s2 < 4; s2++) { dn[s2] = 0.0f; ps[s2] = 0.0f; pc[s2] = 0.0f; }

    CP_WAIT0();
    __syncthreads();

    for (int t = t0; t < t1; t++) {
        const int s = t & 1;
        const bool have_next = (t + 1) < t1;

        // next tile indices
        int nti = ti, ntj = tj + 1;
        if (ntj == 64) { nti = ti + 1; ntj = nti; }

        // prefetch B(t+1) + labels(t+1)
        if (have_next) {
            cp_tile(sb + SM_B + ((t + 1) & 1) * 32768, ntj * 128, tid);
            if (tid < 32) {
                size_t lsrc = __cvta_generic_to_global(labels) + (size_t)ntj * 512;
                CP_ASYNC16(sb + SM_LAB + ((t + 1) & 1) * 512 + tid * 16,
                           (const void*)(lsrc + tid * 16));
            }
            CP_COMMIT();
        }

        // ---- mainloop: 128x128 tile, K=128, warp tile 32x32 ----
        float acc[2][4][4];
        #pragma unroll
        for (int mi = 0; mi < 2; mi++)
            #pragma unroll
            for (int ni = 0; ni < 4; ni++)
                #pragma unroll
                for (int r = 0; r < 4; r++) acc[mi][ni][r] = 0.0f;

        const uint32_t bBase = sb + SM_B + s * 32768 + bRowOff;
        #pragma unroll
        for (int k = 0; k < 8; k++) {
            uint32_t a[2][4];
            #pragma unroll
            for (int mi = 0; mi < 2; mi++) {
                uint32_t addr = aBase + mi * 4096 + ((((k * 2 + hiA) ^ r7A)) << 4);
                LDSM_X4(a[mi][0], a[mi][1], a[mi][2], a[mi][3], addr);
            }
            uint32_t b[4][2];
            #pragma unroll
            for (int p = 0; p < 2; p++) {
                uint32_t addr = bBase + p * 4096 + ((((k * 2 + segbLo) ^ r8)) << 4);
                LDSM_X4(b[2 * p][0], b[2 * p][1], b[2 * p + 1][0], b[2 * p + 1][1], addr);
            }
            #pragma unroll
            for (int mi = 0; mi < 2; mi++)
                #pragma unroll
                for (int ni = 0; ni < 4; ni++)
                    MMA16816(acc[mi][ni], a[mi], b[ni]);
        }

        // ---- fused epilogue ----
        {
            const int jb = tj * 128;
            const float* slab = (const float*)(smem + SM_LAB + s * 512);

            if (jb == ibase) {
                // diagonal tile: row stats only, with self-exclusion
                #pragma unroll
                for (int mi = 0; mi < 2; mi++) {
                    #pragma unroll
                    for (int rh = 0; rh < 2; rh++) {
                        const int slot = mi * 2 + rh;
                        const int selfnl = wm * 32 + mi * 16 + quad + rh * 8;
                        const float lm = li[slot];
                        float dnl = 0.0f, psl = 0.0f, pcl = 0.0f;
                        #pragma unroll
                        for (int ni = 0; ni < 4; ni++) {
                            #pragma unroll
                            for (int c = 0; c < 2; c++) {
                                float sv = acc[mi][ni][rh * 2 + c] * INV_T;
                                const int nl = wn * 32 + ni * 8 + qt * 2 + c;
                                float lj = slab[nl];
                                bool self = (nl == selfnl);
                                float e = __expf(sv);
                                dnl += self ? 0.0f : e;
                                bool pos = (fabsf(lm - lj) < THRESH) && !self;
                                psl += pos ? sv : 0.0f;
                                pcl += pos ? 1.0f : 0.0f;
                            }
                        }
                        dn[slot] += dnl; ps[slot] += psl; pc[slot] += pcl;
                    }
                }
            } else {
                // off-diagonal tile: row stats + column stats, no self possible
                #pragma unroll
                for (int ni = 0; ni < 4; ni++) {
                    #pragma unroll
                    for (int c = 0; c < 2; c++) {
                        const int nl = wn * 32 + ni * 8 + qt * 2 + c;
                        const float lj = slab[nl];
                        float cdn = 0.0f, cps = 0.0f, cpc = 0.0f;
                        #pragma unroll
                        for (int mi = 0; mi < 2; mi++) {
                            #pragma unroll
                            for (int rh = 0; rh < 2; rh++) {
                                const int slot = mi * 2 + rh;
                                float sv = acc[mi][ni][rh * 2 + c] * INV_T;
                                float e = __expf(sv);
                                dn[slot] += e;
                                cdn += e;
                                bool pos = fabsf(li[slot] - lj) < THRESH;
                                float svp = pos ? sv : 0.0f;
                                float onep = pos ? 1.0f : 0.0f;
                                ps[slot] += svp;  cps += svp;
                                pc[slot] += onep; cpc += onep;
                            }
                        }
                        // reduce column stats across the 8 quad-lanes (stride 4)
                        #pragma unroll
                        for (int off = 4; off <= 16; off <<= 1) {
                            cdn += __shfl_xor_sync(0xffffffffu, cdn, off);
                            cps += __shfl_xor_sync(0xffffffffu, cps, off);
                            cpc += __shfl_xor_sync(0xffffffffu, cpc, off);
                        }
                        if (quad == 0) {
                            atomicAdd(&g_den[jb + nl], cdn);
                            atomicAdd(&g_ps[jb + nl],  cps);
                            atomicAdd(&g_pc[jb + nl],  cpc);
                        }
                    }
                }
            }
        }

        const bool ichange = have_next && (nti != ti);

        // flush row stats at i-row boundary / end
        if (ichange || !have_next) {
            #pragma unroll
            for (int s2 = 0; s2 < 4; s2++) {
                float a = dn[s2], b = ps[s2], c = pc[s2];
                a += __shfl_xor_sync(0xffffffffu, a, 1);
                a += __shfl_xor_sync(0xffffffffu, a, 2);
                b += __shfl_xor_sync(0xffffffffu, b, 1);
                b += __shfl_xor_sync(0xffffffffu, b, 2);
                c += __shfl_xor_sync(0xffffffffu, c, 1);
                c += __shfl_xor_sync(0xffffffffu, c, 2);
                if (qt == 0) {
                    int gim = ibase + wm * 32 + (s2 >> 1) * 16 + quad + (s2 & 1) * 8;
                    atomicAdd(&g_den[gim], a);
                    atomicAdd(&g_ps[gim],  b);
                    atomicAdd(&g_pc[gim],  c);
                }
                dn[s2] = 0.0f; ps[s2] = 0.0f; pc[s2] = 0.0f;
            }
        }

        CP_WAIT0();            // B(t+1)/labels(t+1) landed
        __syncthreads();       // visible to all; slab readers done

        if (ichange) {
            ibase = nti * 128;
            cp_tile(sb + SM_A, ibase, tid);
            CP_COMMIT();
            #pragma unroll
            for (int s2 = 0; s2 < 4; s2++)
                li[s2] = labels[ibase + wm * 32 + (s2 >> 1) * 16 + quad + (s2 & 1) * 8];
            CP_WAIT0();
            __syncthreads();
        }
        ti = nti; tj = ntj;
    }

    // ---- last CTA computes the final loss (threadfence + counter pattern) ----
    __threadfence();
    __syncthreads();
    __shared__ unsigned int s_ticket;
    if (tid == 0) s_ticket = atomicAdd(&g_done, 1u);
    __syncthreads();
    if (s_ticket == NCTA - 1) {
        __threadfence();
        float* red = (float*)smem;
        float local = 0.0f;
        for (int i = tid; i < N; i += NTHR)
            local += g_ps[i] / g_pc[i] - logf(g_den[i]);
        red[tid] = local;
        __syncthreads();
        #pragma unroll
        for (int sft = NTHR / 2; sft; sft >>= 1) {
            if (tid < sft) red[tid] += red[tid + sft];
            __syncthreads();
        }
        if (tid == 0) out[0] = -red[0] / (float)N;
    }
}

// ---------------------------------------------------------------------------
extern "C" void kernel_launch(void* const* d_in, const int* in_sizes, int n_in,
                              void* d_out, int out_size) {
    const float* features = (const float*)d_in[0];
    const float* labels   = (const float*)d_in[1];
    float* out = (float*)d_out;

    cudaFuncSetAttribute(main_kernel, cudaFuncAttributeMaxDynamicSharedMemorySize, SM_TOTAL);

    prep_kernel<<<N / 8, 256>>>(features);
    main_kernel<<<NCTA, NTHR, SM_TOTAL>>>(labels, out);
}

// round 6
// speedup vs baseline: 6.4073x; 1.1039x over previous
#include <cuda_runtime.h>
#include <cuda_bf16.h>
#include <cstdint>
#include <math.h>

#define N 8192
#define D 128
#define NCTA 148
#define NTT 2080               /* upper-triangle tiles: 64*65/2 */
#define NTHR 512
#define C_LOG2 20.60992915555662f   /* (1/0.07) * log2(e) */
#define LN2 0.69314718055994531f
#define THRESH 0.1f

// Scratch (no cudaMalloc allowed)
__device__ __nv_bfloat16 g_fbf[N * D];   // normalized features, bf16, row-major
__device__ float g_den[N];
__device__ float g_ps[N];                // in log2 units (xLN2 at finalize)
__device__ float g_pc[N];
__device__ unsigned int g_done;

// ---- SMEM layout (bytes) ----
#define SM_RES   0          /* resident B tile (j-strip), 32 KB, XOR-swizzled */
#define SM_STR   32768      /* 2 x 32 KB double-buffered streaming A tiles */
#define SM_LABI  98304      /* 2 x 512B double-buffered row labels */
#define SM_LABJ  99328      /* 512B column labels (per strip) */
#define SM_TOTAL 99840

__device__ __forceinline__ uint32_t smem_u32(const void* p) {
    uint32_t a;
    asm("{ .reg .u64 t; cvta.to.shared.u64 t, %1; cvt.u32.u64 %0, t; }" : "=r"(a) : "l"(p));
    return a;
}
__device__ __forceinline__ float ex2(float x) {
    float r;
    asm("ex2.approx.ftz.f32 %0, %1;" : "=f"(r) : "f"(x));
    return r;
}

#define LDSM_X4(r0, r1, r2, r3, addr) \
    asm volatile("ldmatrix.sync.aligned.m8n8.x4.shared.b16 {%0,%1,%2,%3}, [%4];" \
                 : "=r"(r0), "=r"(r1), "=r"(r2), "=r"(r3) : "r"(addr))

#define MMA16816(d, a, b) \
    asm volatile("mma.sync.aligned.m16n8k16.row.col.f32.bf16.bf16.f32 " \
                 "{%0,%1,%2,%3}, {%4,%5,%6,%7}, {%8,%9}, {%0,%1,%2,%3};" \
                 : "+f"((d)[0]), "+f"((d)[1]), "+f"((d)[2]), "+f"((d)[3]) \
                 : "r"((a)[0]), "r"((a)[1]), "r"((a)[2]), "r"((a)[3]), \
                   "r"((b)[0]), "r"((b)[1]))

#define CP_ASYNC16(dst, src) \
    asm volatile("cp.async.cg.shared.global [%0], [%1], 16;" \
                 :: "r"(dst), "l"(src) : "memory")
#define CP_COMMIT() asm volatile("cp.async.commit_group;" ::: "memory")
#define CP_WAIT0()  asm volatile("cp.async.wait_group 0;" ::: "memory")

// swizzled byte offset of (row, 16B-segment) in a 128x256B tile
__device__ __forceinline__ uint32_t swz(int row, int seg) {
    return (uint32_t)(row * 256 + ((seg ^ (row & 7)) << 4));
}

// cp.async a full 128x256B tile (rows rowBase..+127 of g_fbf) into smem
__device__ __forceinline__ void cp_tile(uint32_t dst_base, int rowBase, int tid) {
    size_t gsrc = __cvta_generic_to_global(g_fbf) + (size_t)rowBase * 256;
    #pragma unroll
    for (int it = 0; it < 4; it++) {
        int u = it * NTHR + tid;         // 16B units, 16 per row, 2048 total
        int row = u >> 4, seg = u & 15;
        CP_ASYNC16(dst_base + swz(row, seg), (const void*)(gsrc + (size_t)u * 16));
    }
}

// ---------------------------------------------------------------------------
// Kernel 1: normalize rows (clamp at 1e-8), quantize to bf16, zero accumulators
// ---------------------------------------------------------------------------
__global__ void prep_kernel(const float* __restrict__ features) {
    int warp = threadIdx.x >> 5, lane = threadIdx.x & 31;
    int row = blockIdx.x * 8 + warp;

    float4 v = ((const float4*)(features + row * D))[lane];
    float ss = v.x * v.x + v.y * v.y + v.z * v.z + v.w * v.w;
    #pragma unroll
    for (int off = 16; off; off >>= 1) ss += __shfl_xor_sync(0xffffffffu, ss, off);
    float sc = 1.0f / fmaxf(sqrtf(ss), 1e-8f);

    __nv_bfloat162 p0 = __floats2bfloat162_rn(v.x * sc, v.y * sc);
    __nv_bfloat162 p1 = __floats2bfloat162_rn(v.z * sc, v.w * sc);
    uint2 st;
    st.x = *(const uint32_t*)&p0;
    st.y = *(const uint32_t*)&p1;
    ((uint2*)(g_fbf + (size_t)row * D))[lane] = st;

    int gt = blockIdx.x * blockDim.x + threadIdx.x;
    if (gt < N) { g_den[gt] = 0.0f; g_ps[gt] = 0.0f; g_pc[gt] = 0.0f; }
    if (gt == 0) g_done = 0;
}

// ---------------------------------------------------------------------------
// Kernel 2: persistent fused HMMA GEMM, COLUMN-MAJOR upper-triangle walk.
// CTA holds a resident j-strip tile (B) and streams i-tiles (A). Column
// stats live in registers across the strip (one shuffle-flush per strip);
// row stats flush per tile with a cheap 2-round shuffle.
// ---------------------------------------------------------------------------
__global__ void __launch_bounds__(NTHR, 1)
main_kernel(const float* __restrict__ labels, float* __restrict__ out) {
    extern __shared__ char smem[];
    const uint32_t sb = smem_u32(smem);
    const int tid  = threadIdx.x;
    const int wid  = tid >> 5;
    const int lane = tid & 31;
    const int wm = wid & 3;          // 0..3 -> m-block of 32
    const int wn = wid >> 2;         // 0..3 -> n-block of 32
    const int quad = lane >> 2;
    const int qt   = lane & 3;

    // --- ldmatrix per-lane bases ---
    const int rowA = wm * 32 + (lane & 15);
    const int hiA  = lane >> 4;
    const int r7A  = rowA & 7;
    const uint32_t aRowOff = (uint32_t)(rowA * 256);
    const int g   = lane >> 3;
    const int r8  = lane & 7;
    const int nrowb = wn * 32 + ((g >> 1) << 3) + r8;  // + p*16 later
    const int segbLo = g & 1;
    const uint32_t bBase = sb + SM_RES + (uint32_t)(nrowb * 256);

    const int t0 = ((int)blockIdx.x * NTT) / NCTA;
    const int t1 = (((int)blockIdx.x + 1) * NTT) / NCTA;

    // map t0 -> (tj, ti): column-major triangle, strip tj has tj+1 tiles
    int tj = 0, rem = t0;
    while (rem >= tj + 1) { rem -= tj + 1; tj++; }
    int ti = rem;

    // prologue: resident B(tj) + column labels + first A(ti) + row labels
    cp_tile(sb + SM_RES, tj * 128, tid);
    cp_tile(sb + SM_STR + (t0 & 1) * 32768, ti * 128, tid);
    {
        size_t lj_src = __cvta_generic_to_global(labels) + (size_t)tj * 512;
        size_t li_src = __cvta_generic_to_global(labels) + (size_t)ti * 512;
        if (tid < 32) CP_ASYNC16(sb + SM_LABJ + tid * 16, (const void*)(lj_src + tid * 16));
        else if (tid < 64)
            CP_ASYNC16(sb + SM_LABI + (t0 & 1) * 512 + (tid - 32) * 16,
                       (const void*)(li_src + (tid - 32) * 16));
    }
    CP_COMMIT();
    CP_WAIT0();
    __syncthreads();

    // column labels for my 8 (ni,c) pairs
    float lj[8];
    #pragma unroll
    for (int p = 0; p < 8; p++)
        lj[p] = ((const float*)(smem + SM_LABJ))[wn * 32 + (p >> 1) * 8 + qt * 2 + (p & 1)];

    // column partials (in registers across the strip)
    float cdn[8], cps[8], cpc[8];
    #pragma unroll
    for (int p = 0; p < 8; p++) { cdn[p] = 0.0f; cps[p] = 0.0f; cpc[p] = 0.0f; }

    for (int t = t0; t < t1; t++) {
        const int s = t & 1;
        const bool have_next = (t + 1) < t1;

        int nti = ti + 1, ntj = tj;
        if (nti > tj) { ntj = tj + 1; nti = 0; }
        const bool strip_change = have_next && (ntj != tj);

        // prefetch A(t+1) + row labels(t+1)
        if (have_next) {
            cp_tile(sb + SM_STR + ((t + 1) & 1) * 32768, nti * 128, tid);
            if (tid < 32) {
                size_t lsrc = __cvta_generic_to_global(labels) + (size_t)nti * 512;
                CP_ASYNC16(sb + SM_LABI + ((t + 1) & 1) * 512 + tid * 16,
                           (const void*)(lsrc + tid * 16));
            }
            CP_COMMIT();
        }

        // ---- mainloop: 128x128 tile, K=128 ----
        float acc[2][4][4];
        #pragma unroll
        for (int mi = 0; mi < 2; mi++)
            #pragma unroll
            for (int ni = 0; ni < 4; ni++)
                #pragma unroll
                for (int r = 0; r < 4; r++) acc[mi][ni][r] = 0.0f;

        const uint32_t aBase = sb + SM_STR + s * 32768 + aRowOff;
        #pragma unroll
        for (int k = 0; k < 8; k++) {
            uint32_t a[2][4];
            #pragma unroll
            for (int mi = 0; mi < 2; mi++) {
                uint32_t addr = aBase + mi * 4096 + ((((k * 2 + hiA) ^ r7A)) << 4);
                LDSM_X4(a[mi][0], a[mi][1], a[mi][2], a[mi][3], addr);
            }
            uint32_t b[4][2];
            #pragma unroll
            for (int p = 0; p < 2; p++) {
                uint32_t addr = bBase + p * 4096 + ((((k * 2 + segbLo) ^ r8)) << 4);
                LDSM_X4(b[2 * p][0], b[2 * p][1], b[2 * p + 1][0], b[2 * p + 1][1], addr);
            }
            #pragma unroll
            for (int mi = 0; mi < 2; mi++)
                #pragma unroll
                for (int ni = 0; ni < 4; ni++)
                    MMA16816(acc[mi][ni], a[mi], b[ni]);
        }

        // row labels for my 4 m-slots
        const float* slabI = (const float*)(smem + SM_LABI + s * 512);
        float li[4];
        #pragma unroll
        for (int s2 = 0; s2 < 4; s2++)
            li[s2] = slabI[wm * 32 + (s2 >> 1) * 16 + quad + (s2 & 1) * 8];

        // ---- fused epilogue (u = sim * log2e/T; exp(sim) = ex2(u)) ----
        float dn[4] = {0, 0, 0, 0}, ps[4] = {0, 0, 0, 0}, pc[4] = {0, 0, 0, 0};
        if (ti == tj) {
            // diagonal tile: row stats only, with self-exclusion
            #pragma unroll
            for (int mi = 0; mi < 2; mi++) {
                #pragma unroll
                for (int rh = 0; rh < 2; rh++) {
                    const int slot = mi * 2 + rh;
                    const int selfnl = wm * 32 + mi * 16 + quad + rh * 8;
                    const float lm = li[slot];
                    #pragma unroll
                    for (int p = 0; p < 8; p++) {
                        const int ni = p >> 1, c = p & 1;
                        float u = acc[mi][ni][rh * 2 + c] * C_LOG2;
                        const int nl = wn * 32 + ni * 8 + qt * 2 + c;
                        bool self = (nl == selfnl);
                        float e = ex2(u);
                        dn[slot] += self ? 0.0f : e;
                        bool pos = (fabsf(lm - lj[p]) < THRESH) && !self;
                        ps[slot] += pos ? u : 0.0f;
                        pc[slot] += pos ? 1.0f : 0.0f;
                    }
                }
            }
        } else {
            // off-diagonal tile: row + column stats, no self possible
            #pragma unroll
            for (int p = 0; p < 8; p++) {
                const int ni = p >> 1, c = p & 1;
                const float ljp = lj[p];
                float a0 = 0.0f, a1 = 0.0f, a2 = 0.0f;
                #pragma unroll
                for (int mi = 0; mi < 2; mi++) {
                    #pragma unroll
                    for (int rh = 0; rh < 2; rh++) {
                        const int slot = mi * 2 + rh;
                        float u = acc[mi][ni][rh * 2 + c] * C_LOG2;
                        float e = ex2(u);
                        dn[slot] += e;
                        a0 += e;
                        bool pos = fabsf(li[slot] - ljp) < THRESH;
                        float up = pos ? u : 0.0f;
                        float op = pos ? 1.0f : 0.0f;
                        ps[slot] += up;  a1 += up;
                        pc[slot] += op;  a2 += op;
                    }
                }
                cdn[p] += a0; cps[p] += a1; cpc[p] += a2;
            }
        }

        // ---- row flush: every tile (rows change each tile). 2-round shuffle.
        #pragma unroll
        for (int s2 = 0; s2 < 4; s2++) {
            float a = dn[s2], b = ps[s2], c = pc[s2];
            a += __shfl_xor_sync(0xffffffffu, a, 1);
            a += __shfl_xor_sync(0xffffffffu, a, 2);
            b += __shfl_xor_sync(0xffffffffu, b, 1);
            b += __shfl_xor_sync(0xffffffffu, b, 2);
            c += __shfl_xor_sync(0xffffffffu, c, 1);
            c += __shfl_xor_sync(0xffffffffu, c, 2);
            if (qt == 0) {
                int gim = ti * 128 + wm * 32 + (s2 >> 1) * 16 + quad + (s2 & 1) * 8;
                atomicAdd(&g_den[gim], a);
                atomicAdd(&g_ps[gim],  b);
                atomicAdd(&g_pc[gim],  c);
            }
        }

        // ---- column flush at strip end / range end (3-round shuffle) ----
        if (strip_change || !have_next) {
            #pragma unroll
            for (int p = 0; p < 8; p++) {
                float a = cdn[p], b = cps[p], c = cpc[p];
                #pragma unroll
                for (int off = 4; off <= 16; off <<= 1) {
                    a += __shfl_xor_sync(0xffffffffu, a, off);
                    b += __shfl_xor_sync(0xffffffffu, b, off);
                    c += __shfl_xor_sync(0xffffffffu, c, off);
                }
                if (quad == 0) {
                    int gj = tj * 128 + wn * 32 + (p >> 1) * 8 + qt * 2 + (p & 1);
                    atomicAdd(&g_den[gj], a);
                    atomicAdd(&g_ps[gj],  b);
                    atomicAdd(&g_pc[gj],  c);
                }
                cdn[p] = 0.0f; cps[p] = 0.0f; cpc[p] = 0.0f;
            }
        }

        CP_WAIT0();            // A(t+1)/labels(t+1) landed
        __syncthreads();       // visible to all; RES/LABJ readers done

        if (strip_change) {
            // load new resident B strip + its column labels
            cp_tile(sb + SM_RES, ntj * 128, tid);
            if (tid < 32) {
                size_t lsrc = __cvta_generic_to_global(labels) + (size_t)ntj * 512;
                CP_ASYNC16(sb + SM_LABJ + tid * 16, (const void*)(lsrc + tid * 16));
            }
            CP_COMMIT();
            CP_WAIT0();
            __syncthreads();
            #pragma unroll
            for (int p = 0; p < 8; p++)
                lj[p] = ((const float*)(smem + SM_LABJ))[wn * 32 + (p >> 1) * 8 + qt * 2 + (p & 1)];
        }
        ti = nti; tj = ntj;
    }

    // ---- last CTA computes the final loss (threadfence + counter pattern) ----
    __threadfence();
    __syncthreads();
    __shared__ unsigned int s_ticket;
    if (tid == 0) s_ticket = atomicAdd(&g_done, 1u);
    __syncthreads();
    if (s_ticket == NCTA - 1) {
        __threadfence();
        float* red = (float*)smem;
        float local = 0.0f;
        for (int i = tid; i < N; i += NTHR)
            local += g_ps[i] / g_pc[i] - log2f(g_den[i]);
        red[tid] = local;
        __syncthreads();
        #pragma unroll
        for (int sft = NTHR / 2; sft; sft >>= 1) {
            if (tid < sft) red[tid] += red[tid + sft];
            __syncthreads();
        }
        if (tid == 0) out[0] = -(LN2 * red[0]) / (float)N;
    }
}

// ---------------------------------------------------------------------------
extern "C" void kernel_launch(void* const* d_in, const int* in_sizes, int n_in,
                              void* d_out, int out_size) {
    const float* features = (const float*)d_in[0];
    const float* labels   = (const float*)d_in[1];
    float* out = (float*)d_out;

    cudaFuncSetAttribute(main_kernel, cudaFuncAttributeMaxDynamicSharedMemorySize, SM_TOTAL);

    prep_kernel<<<N / 8, 256>>>(features);
    main_kernel<<<NCTA, NTHR, SM_TOTAL>>>(labels, out);
}